// round 12
// baseline (speedup 1.0000x reference)
#include <cuda_runtime.h>
#include <cuda_fp16.h>
#include <cstdint>
#include <cstddef>

#define BATCH 32
#define SEQ   2048
#define DIM   128
#define QT    64
#define KT    32
#define NT    128
#define HYST  6.0f

// smem: Q hi/lo 16KB each; K stages: (hi 8KB + lo 8KB) x 2
#define QH_OFF 0
#define QL_OFF 16384
#define KH_OFF(s) (32768 + (s)*16384)
#define KL_OFF(s) (40960 + (s)*16384)
static constexpr int SMEM_BYTES = 65536;

// pre-split fp16 hi/lo copies (u32 = packed half2), [b][seq][d]
#define NPAIR (BATCH*SEQ*DIM/2)
__device__ uint32_t qh_g[NPAIR];
__device__ uint32_t ql_g[NPAIR];
__device__ uint32_t kh_g[NPAIR];
__device__ uint32_t kl_g[NPAIR];

#define MMA(C, A0, A1, A2, A3, B0, B1)                                  \
    asm volatile("mma.sync.aligned.m16n8k16.row.col.f32.f16.f16.f32 "   \
        "{%0,%1,%2,%3}, {%4,%5,%6,%7}, {%8,%9}, {%0,%1,%2,%3};"         \
        : "+f"(C[0]), "+f"(C[1]), "+f"(C[2]), "+f"(C[3])                \
        : "r"(A0), "r"(A1), "r"(A2), "r"(A3), "r"(B0), "r"(B1))

__device__ __forceinline__ void ldsm4(uint32_t& a, uint32_t& b, uint32_t& c,
                                      uint32_t& d, uint32_t addr)
{
    asm volatile("ldmatrix.sync.aligned.m8n8.x4.shared.b16 {%0,%1,%2,%3},[%4];"
                 : "=r"(a), "=r"(b), "=r"(c), "=r"(d) : "r"(addr));
}
__device__ __forceinline__ void ldsm4t(uint32_t& a, uint32_t& b, uint32_t& c,
                                       uint32_t& d, uint32_t addr)
{
    asm volatile("ldmatrix.sync.aligned.m8n8.x4.trans.shared.b16 {%0,%1,%2,%3},[%4];"
                 : "=r"(a), "=r"(b), "=r"(c), "=r"(d) : "r"(addr));
}
__device__ __forceinline__ void cp16(uint32_t dst, const void* src)
{
    asm volatile("cp.async.cg.shared.global [%0], [%1], 16;" :: "r"(dst), "l"(src));
}
#define CP_COMMIT()  asm volatile("cp.async.commit_group;")
#define CP_WAIT1()   asm volatile("cp.async.wait_group 1;")

__device__ __forceinline__ uint2 lds64(uint32_t addr)
{
    uint2 v;
    asm volatile("ld.shared.v2.u32 {%0,%1}, [%2];" : "=r"(v.x), "=r"(v.y) : "r"(addr));
    return v;
}

// reconstruct 2 fp32 from packed hi/lo half2 (x = hi + lo)
__device__ __forceinline__ float2 rec2(uint32_t h, uint32_t l)
{
    float2 a = __half22float2(*(__half2*)&h);
    float2 b = __half22float2(*(__half2*)&l);
    return make_float2(a.x + b.x, a.y + b.y);
}

// split (a,b) fp32 -> packed fp16 hi pair + lo pair (x = hi + lo)
__device__ __forceinline__ void split2(float a, float b, uint32_t& hi, uint32_t& lo)
{
    __half ha = __float2half_rn(a), hb = __float2half_rn(b);
    __half la = __float2half_rn(a - __half2float(ha));
    __half lb = __float2half_rn(b - __half2float(hb));
    __half2 H = __halves2half2(ha, hb);
    __half2 L = __halves2half2(la, lb);
    hi = *(uint32_t*)&H;
    lo = *(uint32_t*)&L;
}

// ---------------------------------------------------------------------------
// JAX threefry-2x32 (partitionable fold), key=(0,42). Verified R1-R11.
// ---------------------------------------------------------------------------
__device__ __forceinline__ uint32_t threefry_bits(uint32_t idx)
{
    uint32_t x0 = 0u;
    uint32_t x1 = idx + 42u;
    const uint32_t ks1 = 42u;
    const uint32_t ks2 = 0x1BD11BDAu ^ 42u;

#define TF_R4(a,b,c,d)                                          \
    x0 += x1; x1 = __funnelshift_l(x1, x1, (a)); x1 ^= x0;      \
    x0 += x1; x1 = __funnelshift_l(x1, x1, (b)); x1 ^= x0;      \
    x0 += x1; x1 = __funnelshift_l(x1, x1, (c)); x1 ^= x0;      \
    x0 += x1; x1 = __funnelshift_l(x1, x1, (d)); x1 ^= x0;

    TF_R4(13,15,26, 6)  x0 += ks1;  x1 += ks2 + 1u;
    TF_R4(17,29,16,24)  x0 += ks2;  x1 += 2u;
    TF_R4(13,15,26, 6)              x1 += ks1 + 3u;
    TF_R4(17,29,16,24)  x0 += ks1;  x1 += ks2 + 4u;
    TF_R4(13,15,26, 6)  x0 += ks2;  x1 += 5u;
#undef TF_R4
    return x0 ^ x1;
}

__global__ void split_kernel(const float2* __restrict__ x1,
                             const float2* __restrict__ x2)
{
    const float SCALE = 3.36358566f;   // 128**0.25 folded into Q
    int i = blockIdx.x * blockDim.x + threadIdx.x;
    float2 q = x1[i];
    float2 k = x2[i];
    uint32_t h, l;
    split2(q.x * SCALE, q.y * SCALE, h, l);
    qh_g[i] = h; ql_g[i] = l;
    split2(k.x, k.y, h, l);
    kh_g[i] = h; kl_g[i] = l;
}

// smem tile: rows x 256B (128 fp16), 16B chunks XOR-swizzled by row&7
template <int CHUNKS>
__device__ __forceinline__ void load_tile(uint32_t dstH, uint32_t dstL,
                                          const char* srcH, const char* srcL,
                                          int tid)
{
#pragma unroll
    for (int j = 0; j < CHUNKS / NT; ++j) {
        const int c   = tid + j * NT;
        const int row = c >> 4, ch = c & 15;
        const uint32_t off = row * 256 + ((ch ^ (row & 7)) << 4);
        cp16(dstH + off, srcH + c * 16);
        cp16(dstL + off, srcL + c * 16);
    }
}

// ---------------------------------------------------------------------------
// Sparse-exact flash attention. 4 warps, QT=64, KT=32, 3 CTAs/SM.
// QK^T: ONE fp16 product (qh*kh) -> approx S (logit sigma ~0.02), used only
// to find the row max and gate candidates (margin 0.25 = 13 sigma). Entries
// above the gate (~2-4 per warp-tile) are recomputed EXACTLY in fp32 by the
// whole warp cooperatively from smem (q=qh+ql, k=kh+kl, 2^-22 accurate).
// Softmax l / P use only exact candidate values (sub-gate mass < 2e-5 of l).
// PV: 1 product (Ph*Vh), ~2e-4 rel err (R8-verified). PV+pack skipped when
// a warp-tile has no candidates.
// ---------------------------------------------------------------------------
__global__ void __launch_bounds__(NT, 3)
attn_kernel(float* __restrict__ out)
{
    extern __shared__ char smc[];
    const uint32_t smem = (uint32_t)__cvta_generic_to_shared(smc);

    const int b    = blockIdx.y;
    const int qt0  = blockIdx.x * QT;
    const int tid  = threadIdx.x;
    const int w    = tid >> 5;
    const int lane = tid & 31;
    const int g    = lane >> 2;
    const int p    = lane & 3;
    const int lane7 = lane & 7;
    const int sub   = lane >> 3;

    // ldmatrix addressing (row&7 == lane7 for all types):
    const int rA = lane7 + ((sub & 1) << 3);   // A-frag / trans-B row add
    const int cA = sub >> 1;                   // chunk add
    const int rB = lane7 + ((sub >> 1) << 3);  // B-frag (QK) row add
    const int cB = sub & 1;

    // per-lane 8B offset within a 256B row (for candidate dot; d = 4*lane..+3)
    const uint32_t dsel = ((lane & 1) << 3);
    const int     dchk = lane >> 1;

    const char* qhb = (const char*)qh_g + (size_t)(b*SEQ + qt0) * 256;
    const char* qlb = (const char*)ql_g + (size_t)(b*SEQ + qt0) * 256;
    const char* khb = (const char*)kh_g + (size_t)b * SEQ * 256;
    const char* klb = (const char*)kl_g + (size_t)b * SEQ * 256;

    // prologue: Q + K tile 0 (group 0), K tile 1 (group 1)
    load_tile<QT*16>(smem + QH_OFF, smem + QL_OFF, qhb, qlb, tid);
    load_tile<KT*16>(smem + KH_OFF(0), smem + KL_OFF(0), khb, klb, tid);
    CP_COMMIT();
    load_tile<KT*16>(smem + KH_OFF(1), smem + KL_OFF(1), khb + KT*256, klb + KT*256, tid);
    CP_COMMIT();

    float o[16][4];
    float m0 = -1e30f, m1 = -1e30f, l0 = 0.f, l1 = 0.f;
#pragma unroll
    for (int nt = 0; nt < 16; ++nt)
#pragma unroll
        for (int j = 0; j < 4; ++j) o[nt][j] = 0.f;

    const uint32_t qrow = smem + QH_OFF + (w*16 + rA) * 256;

    for (int t = 0; t < SEQ/KT; ++t) {
        CP_WAIT1();
        __syncthreads();
        const uint32_t kh0 = smem + KH_OFF(t & 1);

        // ---- approx S = Qh Kh^T : ONE product ----
        float s[4][4];
#pragma unroll
        for (int nt = 0; nt < 4; ++nt)
#pragma unroll
            for (int j = 0; j < 4; ++j) s[nt][j] = 0.f;

#pragma unroll
        for (int kc = 0; kc < 8; ++kc) {
            const uint32_t aoff = ((2*kc + cA) ^ lane7) << 4;
            uint32_t qa0, qa1, qa2, qa3;
            ldsm4(qa0, qa1, qa2, qa3, qrow + aoff);

            const uint32_t boff = ((2*kc + cB) ^ lane7) << 4;
#pragma unroll
            for (int n0g = 0; n0g < 2; ++n0g) {
                const uint32_t baddr = kh0 + (n0g*16 + rB) * 256 + boff;
                uint32_t kb0, kb1, kb2, kb3;
                ldsm4(kb0, kb1, kb2, kb3, baddr);
                const int nt = n0g * 2;
                MMA(s[nt],   qa0, qa1, qa2, qa3, kb0, kb1);
                MMA(s[nt+1], qa0, qa1, qa2, qa3, kb2, kb3);
            }
        }

        // ---- hysteresis online max (approx values; m only shifts exp) ----
        float mx0 = -1e30f, mx1 = -1e30f;
#pragma unroll
        for (int nt = 0; nt < 4; ++nt) {
            mx0 = fmaxf(mx0, fmaxf(s[nt][0], s[nt][1]));
            mx1 = fmaxf(mx1, fmaxf(s[nt][2], s[nt][3]));
        }
        mx0 = fmaxf(mx0, __shfl_xor_sync(0xffffffffu, mx0, 1));
        mx0 = fmaxf(mx0, __shfl_xor_sync(0xffffffffu, mx0, 2));
        mx1 = fmaxf(mx1, __shfl_xor_sync(0xffffffffu, mx1, 1));
        mx1 = fmaxf(mx1, __shfl_xor_sync(0xffffffffu, mx1, 2));

        float c0 = 1.f, c1 = 1.f;
        int flag = 0;
        if (mx0 > m0 + HYST) { c0 = __expf(m0 - mx0); m0 = mx0; l0 *= c0; flag = 1; }
        if (mx1 > m1 + HYST) { c1 = __expf(m1 - mx1); m1 = mx1; l1 *= c1; flag = 1; }

        if (__ballot_sync(0xffffffffu, flag)) {   // rare: rescale O
#pragma unroll
            for (int nt = 0; nt < 16; ++nt) {
                o[nt][0] *= c0; o[nt][1] *= c0;
                o[nt][2] *= c1; o[nt][3] *= c1;
            }
        }

        // ---- candidate mask (wide gate, 13-sigma margin) ----
        uint32_t cmask = 0;
#pragma unroll
        for (int nt = 0; nt < 4; ++nt)
#pragma unroll
            for (int j = 0; j < 4; ++j)
                if (s[nt][j] - ((j >= 2) ? m1 : m0) > -18.67f)
                    cmask |= 1u << (nt*4 + j);

        // ---- warp-cooperative exact fp32 recompute of candidates ----
#pragma unroll
        for (int slot = 0; slot < 16; ++slot) {
            uint32_t ball = __ballot_sync(0xffffffffu, (cmask >> slot) & 1u);
            while (ball) {
                const int src = __ffs(ball) - 1;
                ball &= ball - 1;
                const int qr = w*16 + (src >> 2) + ((slot & 2) ? 8 : 0);
                const int kr = ((slot >> 2) << 3) + ((src & 3) << 1) + (slot & 1);
                const uint32_t qa = smem + QH_OFF + qr*256
                                  + (((dchk ^ (qr & 7)) << 4) | dsel);
                const uint32_t ka = kh0 + kr*256
                                  + (((dchk ^ (kr & 7)) << 4) | dsel);
                const uint2 qh8 = lds64(qa);
                const uint2 ql8 = lds64(qa + (QL_OFF - QH_OFF));
                const uint2 kh8 = lds64(ka);
                const uint2 kl8 = lds64(ka + 8192);
                const float2 q01 = rec2(qh8.x, ql8.x), q23 = rec2(qh8.y, ql8.y);
                const float2 k01 = rec2(kh8.x, kl8.x), k23 = rec2(kh8.y, kl8.y);
                float part = q01.x*k01.x;
                part = fmaf(q01.y, k01.y, part);
                part = fmaf(q23.x, k23.x, part);
                part = fmaf(q23.y, k23.y, part);
                part += __shfl_xor_sync(0xffffffffu, part, 16);
                part += __shfl_xor_sync(0xffffffffu, part, 8);
                part += __shfl_xor_sync(0xffffffffu, part, 4);
                part += __shfl_xor_sync(0xffffffffu, part, 2);
                part += __shfl_xor_sync(0xffffffffu, part, 1);
                if (lane == src) s[slot >> 2][slot & 3] = part;
            }
        }

        // ---- exp/RNG/pack + PV only if the warp-tile has any candidate ----
        if (__ballot_sync(0xffffffffu, cmask)) {
            const uint32_t rb0 = (uint32_t)(b*SEQ + qt0 + w*16 + g) * (uint32_t)SEQ
                               + (uint32_t)(t*KT + 2*p);
            const uint32_t rb1 = rb0 + 8u * (uint32_t)SEQ;

            uint32_t ph[4][2];
#pragma unroll
            for (int nt = 0; nt < 4; ++nt) {
                float pm[4];
#pragma unroll
                for (int j = 0; j < 4; ++j) {
                    const bool hi8 = (j >= 2);
                    const float dlt = s[nt][j] - (hi8 ? m1 : m0);
                    float v = 0.f;
                    if (dlt > -18.42f) {   // exact value, true gate
                        const float e = __expf(dlt);
                        if (hi8) l1 += e; else l0 += e;
                        const uint32_t idx = (hi8 ? rb1 : rb0) + nt*8 + (j & 1);
                        const uint32_t bits = threefry_bits(idx);
                        const float u = __uint_as_float((bits >> 9) | 0x3f800000u) - 1.0f;
                        v = (u < 0.9f) ? e : 0.f;
                    }
                    pm[j] = v;
                }
                __half2 h01 = __floats2half2_rn(pm[0], pm[1]);
                __half2 h23 = __floats2half2_rn(pm[2], pm[3]);
                ph[nt][0] = *(uint32_t*)&h01;
                ph[nt][1] = *(uint32_t*)&h23;
            }

            // O += P~ V : 1 product, V == K tile, trans
#pragma unroll
            for (int kc2 = 0; kc2 < 2; ++kc2) {
                const uint32_t pa0 = ph[2*kc2][0],   pa1 = ph[2*kc2][1];
                const uint32_t pa2 = ph[2*kc2+1][0], pa3 = ph[2*kc2+1][1];
                const uint32_t trow = kh0 + (kc2*16 + rA) * 256;
#pragma unroll
                for (int dcp = 0; dcp < 8; ++dcp) {
                    const uint32_t toff = ((2*dcp + cA) ^ lane7) << 4;
                    uint32_t vb0, vb1, vb2, vb3;
                    ldsm4t(vb0, vb1, vb2, vb3, trow + toff);
                    const int nt = dcp * 2;
                    MMA(o[nt],   pa0, pa1, pa2, pa3, vb0, vb1);
                    MMA(o[nt+1], pa0, pa1, pa2, pa3, vb2, vb3);
                }
            }
        }

        __syncthreads();
        if (t + 2 < SEQ/KT)
            load_tile<KT*16>(smem + KH_OFF(t & 1), smem + KL_OFF(t & 1),
                             khb + (size_t)(t + 2) * KT * 256,
                             klb + (size_t)(t + 2) * KT * 256, tid);
        CP_COMMIT();   // empty groups near the tail keep wait_group semantics
    }

    // ---- epilogue ----
    l0 += __shfl_xor_sync(0xffffffffu, l0, 1);
    l0 += __shfl_xor_sync(0xffffffffu, l0, 2);
    l1 += __shfl_xor_sync(0xffffffffu, l1, 1);
    l1 += __shfl_xor_sync(0xffffffffu, l1, 2);
    const float inv0 = 1.0f / (l0 * 0.9f);
    const float inv1 = 1.0f / (l1 * 0.9f);

    const int row0 = qt0 + w*16 + g;
    float2* op0 = (float2*)(out + (size_t)(b*SEQ + row0) * DIM);
    float2* op1 = (float2*)(out + (size_t)(b*SEQ + row0 + 8) * DIM);
#pragma unroll
    for (int nt = 0; nt < 16; ++nt) {
        float2 v0, v1;
        v0.x = o[nt][0] * inv0; v0.y = o[nt][1] * inv0;
        v1.x = o[nt][2] * inv1; v1.y = o[nt][3] * inv1;
        op0[nt*4 + p] = v0;
        op1[nt*4 + p] = v1;
    }
}

extern "C" void kernel_launch(void* const* d_in, const int* in_sizes, int n_in,
                              void* d_out, int out_size)
{
    (void)in_sizes; (void)n_in; (void)out_size;
    const float2* x1 = (const float2*)d_in[0];
    const float2* x2 = (const float2*)d_in[1];
    float* out = (float*)d_out;

    split_kernel<<<NPAIR / 256, 256>>>(x1, x2);

    cudaFuncSetAttribute(attn_kernel,
                         cudaFuncAttributeMaxDynamicSharedMemorySize, SMEM_BYTES);
    dim3 grid(SEQ / QT, BATCH);
    attn_kernel<<<grid, NT, SMEM_BYTES>>>(out);
}

// round 13
// speedup vs baseline: 1.6214x; 1.6214x over previous
#include <cuda_runtime.h>
#include <cuda_fp16.h>
#include <cstdint>
#include <cstddef>

#define BATCH 32
#define SEQ   2048
#define DIM   128
#define QT    64
#define KT    32
#define NT    128
#define NTILES (SEQ/KT)
#define HYST  6.0f

// smem: Q hi/lo 16KB each; kh double-buffer 8KB x2; kl single 8KB
#define QH_OFF 0
#define QL_OFF 16384
#define KH_OFF(s) (32768 + (s)*8192)
#define KL_OFF  49152
static constexpr int SMEM_BYTES = 57344;

// pre-split fp16 hi/lo copies (u32 = packed half2), [b][seq][d]
#define NPAIR (BATCH*SEQ*DIM/2)
__device__ uint32_t qh_g[NPAIR];
__device__ uint32_t ql_g[NPAIR];
__device__ uint32_t kh_g[NPAIR];
__device__ uint32_t kl_g[NPAIR];

#define MMA(C, A0, A1, A2, A3, B0, B1)                                  \
    asm volatile("mma.sync.aligned.m16n8k16.row.col.f32.f16.f16.f32 "   \
        "{%0,%1,%2,%3}, {%4,%5,%6,%7}, {%8,%9}, {%0,%1,%2,%3};"         \
        : "+f"(C[0]), "+f"(C[1]), "+f"(C[2]), "+f"(C[3])                \
        : "r"(A0), "r"(A1), "r"(A2), "r"(A3), "r"(B0), "r"(B1))

__device__ __forceinline__ void ldsm4(uint32_t& a, uint32_t& b, uint32_t& c,
                                      uint32_t& d, uint32_t addr)
{
    asm volatile("ldmatrix.sync.aligned.m8n8.x4.shared.b16 {%0,%1,%2,%3},[%4];"
                 : "=r"(a), "=r"(b), "=r"(c), "=r"(d) : "r"(addr));
}
__device__ __forceinline__ void ldsm4t(uint32_t& a, uint32_t& b, uint32_t& c,
                                       uint32_t& d, uint32_t addr)
{
    asm volatile("ldmatrix.sync.aligned.m8n8.x4.trans.shared.b16 {%0,%1,%2,%3},[%4];"
                 : "=r"(a), "=r"(b), "=r"(c), "=r"(d) : "r"(addr));
}
__device__ __forceinline__ void cp16(uint32_t dst, const void* src)
{
    asm volatile("cp.async.cg.shared.global [%0], [%1], 16;" :: "r"(dst), "l"(src));
}
#define CP_COMMIT()  asm volatile("cp.async.commit_group;")
#define CP_WAIT1()   asm volatile("cp.async.wait_group 1;")

// split (a,b) fp32 -> packed fp16 hi pair + lo pair (x = hi + lo)
__device__ __forceinline__ void split2(float a, float b, uint32_t& hi, uint32_t& lo)
{
    __half ha = __float2half_rn(a), hb = __float2half_rn(b);
    __half la = __float2half_rn(a - __half2float(ha));
    __half lb = __float2half_rn(b - __half2float(hb));
    __half2 H = __halves2half2(ha, hb);
    __half2 L = __halves2half2(la, lb);
    hi = *(uint32_t*)&H;
    lo = *(uint32_t*)&L;
}

// ---------------------------------------------------------------------------
// JAX threefry-2x32 (partitionable fold), key=(0,42). Verified R1-R12.
// ---------------------------------------------------------------------------
__device__ __forceinline__ uint32_t threefry_bits(uint32_t idx)
{
    uint32_t x0 = 0u;
    uint32_t x1 = idx + 42u;
    const uint32_t ks1 = 42u;
    const uint32_t ks2 = 0x1BD11BDAu ^ 42u;

#define TF_R4(a,b,c,d)                                          \
    x0 += x1; x1 = __funnelshift_l(x1, x1, (a)); x1 ^= x0;      \
    x0 += x1; x1 = __funnelshift_l(x1, x1, (b)); x1 ^= x0;      \
    x0 += x1; x1 = __funnelshift_l(x1, x1, (c)); x1 ^= x0;      \
    x0 += x1; x1 = __funnelshift_l(x1, x1, (d)); x1 ^= x0;

    TF_R4(13,15,26, 6)  x0 += ks1;  x1 += ks2 + 1u;
    TF_R4(17,29,16,24)  x0 += ks2;  x1 += 2u;
    TF_R4(13,15,26, 6)              x1 += ks1 + 3u;
    TF_R4(17,29,16,24)  x0 += ks1;  x1 += ks2 + 4u;
    TF_R4(13,15,26, 6)  x0 += ks2;  x1 += 5u;
#undef TF_R4
    return x0 ^ x1;
}

__global__ void split_kernel(const float2* __restrict__ x1,
                             const float2* __restrict__ x2)
{
    const float SCALE = 3.36358566f;   // 128**0.25 folded into Q
    int i = blockIdx.x * blockDim.x + threadIdx.x;
    float2 q = x1[i];
    float2 k = x2[i];
    uint32_t h, l;
    split2(q.x * SCALE, q.y * SCALE, h, l);
    qh_g[i] = h; ql_g[i] = l;
    split2(k.x, k.y, h, l);
    kh_g[i] = h; kl_g[i] = l;
}

// load one array of BYTES into smem: rows x 256B, 16B chunks XOR-swizzled
template <int BYTES>
__device__ __forceinline__ void load_arr(uint32_t dst, const char* src, int tid)
{
#pragma unroll
    for (int j = 0; j < BYTES/16/NT; ++j) {
        const int c   = tid + j * NT;
        const int row = c >> 4, ch = c & 15;
        const uint32_t off = row * 256 + ((ch ^ (row & 7)) << 4);
        cp16(dst + off, src + c * 16);
    }
}

// ---------------------------------------------------------------------------
// fp16 split flash attention. 4 warps, QT=64, KT=32, 4 CTAs/SM (forced
// 128-reg ceiling + 56KB smem: kh double-buffered 2 tiles ahead, kl single-
// buffered 1 tile ahead — kl is read only in the QK phase).
// QK^T: 3 products (qh*kh + ql*kh + qh*kl). PV: 1 product (ph*vh).
// Softmax: hysteresis max, exp+RNG gated to near-max entries (R8-verified).
// ---------------------------------------------------------------------------
__global__ void __launch_bounds__(NT, 4)
attn_kernel(float* __restrict__ out)
{
    extern __shared__ char smc[];
    const uint32_t smem = (uint32_t)__cvta_generic_to_shared(smc);

    const int b    = blockIdx.y;
    const int qt0  = blockIdx.x * QT;
    const int tid  = threadIdx.x;
    const int w    = tid >> 5;
    const int lane = tid & 31;
    const int g    = lane >> 2;
    const int p    = lane & 3;
    const int lane7 = lane & 7;
    const int sub   = lane >> 3;

    // ldmatrix addressing (row&7 == lane7 for all types):
    const int rA = lane7 + ((sub & 1) << 3);   // A-frag / trans-B row add
    const int cA = sub >> 1;                   // chunk add
    const int rB = lane7 + ((sub >> 1) << 3);  // B-frag (QK) row add
    const int cB = sub & 1;

    const char* qhb = (const char*)qh_g + (size_t)(b*SEQ + qt0) * 256;
    const char* qlb = (const char*)ql_g + (size_t)(b*SEQ + qt0) * 256;
    const char* khb = (const char*)kh_g + (size_t)b * SEQ * 256;
    const char* klb = (const char*)kl_g + (size_t)b * SEQ * 256;

    // prologue: G0 = {Q, kh(0), kl(0)}, G1 = {kh(1)}
    load_arr<16384>(smem + QH_OFF, qhb, tid);
    load_arr<16384>(smem + QL_OFF, qlb, tid);
    load_arr<8192>(smem + KH_OFF(0), khb, tid);
    load_arr<8192>(smem + KL_OFF,    klb, tid);
    CP_COMMIT();
    load_arr<8192>(smem + KH_OFF(1), khb + KT*256, tid);
    CP_COMMIT();

    float o[16][4];
    float m0 = -1e30f, m1 = -1e30f, l0 = 0.f, l1 = 0.f;
#pragma unroll
    for (int nt = 0; nt < 16; ++nt)
#pragma unroll
        for (int j = 0; j < 4; ++j) o[nt][j] = 0.f;

    const uint32_t qrow = smem + QH_OFF + (w*16 + rA) * 256;

    for (int t = 0; t < NTILES; ++t) {
        CP_WAIT1();          // kl(t) + kh(t) arrived; kh(t+1) may be in flight
        __syncthreads();
        const uint32_t kh0 = smem + KH_OFF(t & 1);
        const uint32_t kl0 = smem + KL_OFF;

        // ---- S = Q K^T : 3-product fp16 MMA (KT=32 -> 4 n-tiles) ----
        float s[4][4];
#pragma unroll
        for (int nt = 0; nt < 4; ++nt)
#pragma unroll
            for (int j = 0; j < 4; ++j) s[nt][j] = 0.f;

#pragma unroll
        for (int kc = 0; kc < 8; ++kc) {
            const uint32_t aoff = ((2*kc + cA) ^ lane7) << 4;
            uint32_t qa0, qa1, qa2, qa3, la0, la1, la2, la3;
            ldsm4(qa0, qa1, qa2, qa3, qrow + aoff);
            ldsm4(la0, la1, la2, la3, qrow + aoff + (QL_OFF - QH_OFF));

            const uint32_t boff = ((2*kc + cB) ^ lane7) << 4;
#pragma unroll
            for (int n0g = 0; n0g < 2; ++n0g) {
                const uint32_t rowoff = (n0g*16 + rB) * 256 + boff;
                uint32_t kb0, kb1, kb2, kb3, lb0, lb1, lb2, lb3;
                ldsm4(kb0, kb1, kb2, kb3, kh0 + rowoff);
                ldsm4(lb0, lb1, lb2, lb3, kl0 + rowoff);
                const int nt = n0g * 2;
                // interleaved: adjacent MMAs hit different accumulators
                MMA(s[nt],   qa0, qa1, qa2, qa3, kb0, kb1);
                MMA(s[nt+1], qa0, qa1, qa2, qa3, kb2, kb3);
                MMA(s[nt],   la0, la1, la2, la3, kb0, kb1);
                MMA(s[nt+1], la0, la1, la2, la3, kb2, kb3);
                MMA(s[nt],   qa0, qa1, qa2, qa3, lb0, lb1);
                MMA(s[nt+1], qa0, qa1, qa2, qa3, lb2, lb3);
            }
        }

        // ---- hysteresis online max ----
        float mx0 = -1e30f, mx1 = -1e30f;
#pragma unroll
        for (int nt = 0; nt < 4; ++nt) {
            mx0 = fmaxf(mx0, fmaxf(s[nt][0], s[nt][1]));
            mx1 = fmaxf(mx1, fmaxf(s[nt][2], s[nt][3]));
        }
        mx0 = fmaxf(mx0, __shfl_xor_sync(0xffffffffu, mx0, 1));
        mx0 = fmaxf(mx0, __shfl_xor_sync(0xffffffffu, mx0, 2));
        mx1 = fmaxf(mx1, __shfl_xor_sync(0xffffffffu, mx1, 1));
        mx1 = fmaxf(mx1, __shfl_xor_sync(0xffffffffu, mx1, 2));

        float c0 = 1.f, c1 = 1.f;
        int flag = 0;
        if (mx0 > m0 + HYST) { c0 = __expf(m0 - mx0); m0 = mx0; l0 *= c0; flag = 1; }
        if (mx1 > m1 + HYST) { c1 = __expf(m1 - mx1); m1 = mx1; l1 *= c1; flag = 1; }

        if (__ballot_sync(0xffffffffu, flag)) {   // rare: rescale O
#pragma unroll
            for (int nt = 0; nt < 16; ++nt) {
                o[nt][0] *= c0; o[nt][1] *= c0;
                o[nt][2] *= c1; o[nt][3] *= c1;
            }
        }

        // ---- gated exp + threefry dropout; pack P hi (fp16) ----
        const uint32_t rb0 = (uint32_t)(b*SEQ + qt0 + w*16 + g) * (uint32_t)SEQ
                           + (uint32_t)(t*KT + 2*p);
        const uint32_t rb1 = rb0 + 8u * (uint32_t)SEQ;

        uint32_t ph[4][2];
#pragma unroll
        for (int nt = 0; nt < 4; ++nt) {
            float pm[4];
#pragma unroll
            for (int j = 0; j < 4; ++j) {
                const bool hi8 = (j >= 2);
                const float dlt = s[nt][j] - (hi8 ? m1 : m0);
                float v = 0.f;
                if (dlt > -18.42f) {   // p/pmax >= ~1e-8: term matters
                    const float e = __expf(dlt);
                    if (hi8) l1 += e; else l0 += e;
                    const uint32_t idx = (hi8 ? rb1 : rb0) + nt*8 + (j & 1);
                    const uint32_t bits = threefry_bits(idx);
                    const float u = __uint_as_float((bits >> 9) | 0x3f800000u) - 1.0f;
                    v = (u < 0.9f) ? e : 0.f;
                }
                pm[j] = v;
            }
            __half2 h01 = __floats2half2_rn(pm[0], pm[1]);
            __half2 h23 = __floats2half2_rn(pm[2], pm[3]);
            ph[nt][0] = *(uint32_t*)&h01;
            ph[nt][1] = *(uint32_t*)&h23;
        }

        // ---- O += P~ V : 1 product (Ph*Vh), V == K tile, trans ----
#pragma unroll
        for (int kc2 = 0; kc2 < 2; ++kc2) {
            const uint32_t pa0 = ph[2*kc2][0],   pa1 = ph[2*kc2][1];
            const uint32_t pa2 = ph[2*kc2+1][0], pa3 = ph[2*kc2+1][1];
            const uint32_t trow = kh0 + (kc2*16 + rA) * 256;
#pragma unroll
            for (int dcp = 0; dcp < 8; ++dcp) {
                const uint32_t toff = ((2*dcp + cA) ^ lane7) << 4;
                uint32_t vb0, vb1, vb2, vb3;
                ldsm4t(vb0, vb1, vb2, vb3, trow + toff);
                const int nt = dcp * 2;
                MMA(o[nt],   pa0, pa1, pa2, pa3, vb0, vb1);
                MMA(o[nt+1], pa0, pa1, pa2, pa3, vb2, vb3);
            }
        }

        __syncthreads();   // all reads of kl + kh(t-?) stage done
        // kl(t+1): single buffer, 1 tile ahead
        if (t + 1 < NTILES)
            load_arr<8192>(smem + KL_OFF, klb + (size_t)(t + 1) * KT * 256, tid);
        CP_COMMIT();
        // kh(t+2): double buffer, 2 tiles ahead
        if (t + 2 < NTILES)
            load_arr<8192>(smem + KH_OFF(t & 1), khb + (size_t)(t + 2) * KT * 256, tid);
        CP_COMMIT();
    }

    // ---- epilogue ----
    l0 += __shfl_xor_sync(0xffffffffu, l0, 1);
    l0 += __shfl_xor_sync(0xffffffffu, l0, 2);
    l1 += __shfl_xor_sync(0xffffffffu, l1, 1);
    l1 += __shfl_xor_sync(0xffffffffu, l1, 2);
    const float inv0 = 1.0f / (l0 * 0.9f);
    const float inv1 = 1.0f / (l1 * 0.9f);

    const int row0 = qt0 + w*16 + g;
    float2* op0 = (float2*)(out + (size_t)(b*SEQ + row0) * DIM);
    float2* op1 = (float2*)(out + (size_t)(b*SEQ + row0 + 8) * DIM);
#pragma unroll
    for (int nt = 0; nt < 16; ++nt) {
        float2 v0, v1;
        v0.x = o[nt][0] * inv0; v0.y = o[nt][1] * inv0;
        v1.x = o[nt][2] * inv1; v1.y = o[nt][3] * inv1;
        op0[nt*4 + p] = v0;
        op1[nt*4 + p] = v1;
    }
}

extern "C" void kernel_launch(void* const* d_in, const int* in_sizes, int n_in,
                              void* d_out, int out_size)
{
    (void)in_sizes; (void)n_in; (void)out_size;
    const float2* x1 = (const float2*)d_in[0];
    const float2* x2 = (const float2*)d_in[1];
    float* out = (float*)d_out;

    split_kernel<<<NPAIR / 256, 256>>>(x1, x2);

    cudaFuncSetAttribute(attn_kernel,
                         cudaFuncAttributeMaxDynamicSharedMemorySize, SMEM_BYTES);
    dim3 grid(SEQ / QT, BATCH);
    attn_kernel<<<grid, NT, SMEM_BYTES>>>(out);
}